// round 11
// baseline (speedup 1.0000x reference)
#include <cuda_runtime.h>
#include <cuda_fp16.h>
#include <mma.h>

using namespace nvcuda;

#define N_NODES  100000
#define N_EDGES  1600000
#define N_GRAPHS 1000
#define D        64
#define NB_SCAN  ((N_NODES + 255) / 256)   // 391

// ---------------- device scratch (no allocations allowed) ----------------
__device__ int    g_deg[N_NODES];           // in-degree (0-based; self-loop added at use)
__device__ int    g_off[N_NODES];           // CSR row offsets (per-block exclusive scan)
__device__ int    g_cursor[N_NODES];        // fill cursors
__device__ int    g_bsum[NB_SCAN];
__device__ int    g_boff[NB_SCAN];          // block offsets (added at use sites)
__device__ int    g_csr[N_EDGES];           // src indices grouped by dst
__device__ float  g_dinv[N_NODES];          // rsqrt(deg+1)
__device__ __half g_hs[(size_t)N_NODES * D];  // fp16 GEMM outputs (scaled in-place)
__device__ __half g_ha[(size_t)N_NODES * D];  // fp16 aggregation outputs

// ---------------- degree count (deg starts at 0 via memset) ----------------
__global__ void k_deg_count(const int* __restrict__ ei) {
    int t = blockIdx.x * blockDim.x + threadIdx.x;
    if (t < N_EDGES / 4) {
        int4 d = ((const int4*)(ei + N_EDGES))[t];
        atomicAdd(&g_deg[d.x], 1);
        atomicAdd(&g_deg[d.y], 1);
        atomicAdd(&g_deg[d.z], 1);
        atomicAdd(&g_deg[d.w], 1);
    }
}

__global__ void k_dinv() {
    int i = blockIdx.x * blockDim.x + threadIdx.x;
    if (i < N_NODES) g_dinv[i] = rsqrtf((float)(g_deg[i] + 1));
}

// ---------------- 2-pass exclusive scan of deg into off/boff ----------------
__global__ __launch_bounds__(256) void k_scanA() {
    __shared__ int s[256];
    int tid = threadIdx.x;
    int i = blockIdx.x * 256 + tid;
    int v = (i < N_NODES) ? g_deg[i] : 0;
    s[tid] = v;
    __syncthreads();
#pragma unroll
    for (int o = 1; o < 256; o <<= 1) {
        int t = (tid >= o) ? s[tid - o] : 0;
        __syncthreads();
        s[tid] += t;
        __syncthreads();
    }
    if (i < N_NODES) g_off[i] = s[tid] - v;          // exclusive (within block)
    if (tid == 255) g_bsum[blockIdx.x] = s[255];
}

__global__ __launch_bounds__(512) void k_scanB() {
    __shared__ int s[512];
    int tid = threadIdx.x;
    int v = (tid < NB_SCAN) ? g_bsum[tid] : 0;
    s[tid] = v;
    __syncthreads();
#pragma unroll
    for (int o = 1; o < 512; o <<= 1) {
        int t = (tid >= o) ? s[tid - o] : 0;
        __syncthreads();
        s[tid] += t;
        __syncthreads();
    }
    if (tid < NB_SCAN) g_boff[tid] = s[tid] - v;     // exclusive
}

// ---------------- CSR fill: off + boff folded in ----------------
__global__ __launch_bounds__(256) void k_fill(const int* __restrict__ ei) {
    int e = blockIdx.x * blockDim.x + threadIdx.x;
    if (e < N_EDGES) {
        int src = ei[e];
        int dst = ei[N_EDGES + e];
        int pos = g_off[dst] + g_boff[dst >> 8] + atomicAdd(&g_cursor[dst], 1);
        g_csr[pos] = src;
    }
}

// ---------------- GEMM layer 1: hs = fp16( x @ W1 )  (UNSCALED; no dinv dep) ----------------
__global__ __launch_bounds__(256) void k_gemm_l1(const float* __restrict__ in,
                                                 const float* __restrict__ W,
                                                 __half* __restrict__ hs) {
    __shared__ __align__(16) char smem_raw[128 * 68 * 4];
    __half (*Xh)[72] = (__half(*)[72])smem_raw;
    __half (*Wh)[72] = (__half(*)[72])(smem_raw + 18432);
    float  (*Out)[68] = (float(*)[68])smem_raw;

    const int tid = threadIdx.x;
    const int rowBase = blockIdx.x * 128;

#pragma unroll
    for (int i = 0; i < 4; i++) {
        int f4 = tid + i * 256;
        int r  = f4 >> 4;
        int c4 = f4 & 15;
        float4 v = ((const float4*)W)[f4];
        __half2* p = (__half2*)&Wh[r][c4 * 4];
        p[0] = __floats2half2_rn(v.x, v.y);
        p[1] = __floats2half2_rn(v.z, v.w);
    }

#pragma unroll
    for (int i = 0; i < 8; i++) {
        int f4  = tid + i * 256;
        int r   = f4 >> 4;
        int c4  = f4 & 15;
        int row = rowBase + r;
        float4 v = make_float4(0.f, 0.f, 0.f, 0.f);
        if (row < N_NODES) v = ((const float4*)in)[(size_t)row * 16 + c4];
        __half2* p = (__half2*)&Xh[r][c4 * 4];
        p[0] = __floats2half2_rn(v.x, v.y);
        p[1] = __floats2half2_rn(v.z, v.w);
    }
    __syncthreads();

    const int w = tid >> 5;
    wmma::fragment<wmma::accumulator, 16, 16, 16, float> c[4];
#pragma unroll
    for (int cg = 0; cg < 4; cg++) wmma::fill_fragment(c[cg], 0.f);
#pragma unroll
    for (int k = 0; k < 4; k++) {
        wmma::fragment<wmma::matrix_a, 16, 16, 16, __half, wmma::row_major> a;
        wmma::load_matrix_sync(a, &Xh[w * 16][k * 16], 72);
#pragma unroll
        for (int cg = 0; cg < 4; cg++) {
            wmma::fragment<wmma::matrix_b, 16, 16, 16, __half, wmma::row_major> b;
            wmma::load_matrix_sync(b, &Wh[k * 16][cg * 16], 72);
            wmma::mma_sync(c[cg], a, b, c[cg]);
        }
    }
    __syncthreads();
#pragma unroll
    for (int cg = 0; cg < 4; cg++)
        wmma::store_matrix_sync(&Out[w * 16][cg * 16], c[cg], 68, wmma::mem_row_major);
    __syncthreads();

#pragma unroll
    for (int i = 0; i < 4; i++) {
        int idx = tid + i * 256;
        int r   = idx >> 3;
        int q   = idx & 7;
        int row = rowBase + r;
        if (row < N_NODES) {
            const float* src = &Out[r][q * 8];
            __half2 ph[4];
            ph[0] = __floats2half2_rn(src[0], src[1]);
            ph[1] = __floats2half2_rn(src[2], src[3]);
            ph[2] = __floats2half2_rn(src[4], src[5]);
            ph[3] = __floats2half2_rn(src[6], src[7]);
            ((uint4*)hs)[(size_t)row * 8 + q] = *(uint4*)ph;
        }
    }
}

// ---------------- in-place row scale: hs[row,:] *= dinv[row] (fp16) ----------------
__global__ __launch_bounds__(256) void k_scale(__half* __restrict__ hs) {
    int t = blockIdx.x * blockDim.x + threadIdx.x;   // uint4 index (8 halves)
    if (t >= N_NODES * 8) return;
    int node = t >> 3;
    float di = g_dinv[node];
    uint4 v = ((const uint4*)hs)[t];
    float2 f0 = __half22float2(*(__half2*)&v.x);
    float2 f1 = __half22float2(*(__half2*)&v.y);
    float2 f2 = __half22float2(*(__half2*)&v.z);
    float2 f3 = __half22float2(*(__half2*)&v.w);
    __half2 ph[4];
    ph[0] = __floats2half2_rn(f0.x * di, f0.y * di);
    ph[1] = __floats2half2_rn(f1.x * di, f1.y * di);
    ph[2] = __floats2half2_rn(f2.x * di, f2.y * di);
    ph[3] = __floats2half2_rn(f3.x * di, f3.y * di);
    ((uint4*)hs)[t] = *(uint4*)ph;
}

// ---------------- GEMM layer 2: hs = fp16( (ha*dinv[row]) @ W2 ), ha fp16 ----------------
__global__ __launch_bounds__(256) void k_gemm_l2(const __half* __restrict__ in,
                                                 const float* __restrict__ W,
                                                 __half* __restrict__ hs) {
    __shared__ __align__(16) char smem_raw[128 * 68 * 4];
    __half (*Xh)[72] = (__half(*)[72])smem_raw;
    __half (*Wh)[72] = (__half(*)[72])(smem_raw + 18432);
    float  (*Out)[68] = (float(*)[68])smem_raw;

    const int tid = threadIdx.x;
    const int rowBase = blockIdx.x * 128;

#pragma unroll
    for (int i = 0; i < 4; i++) {
        int f4 = tid + i * 256;
        int r  = f4 >> 4;
        int c4 = f4 & 15;
        float4 v = ((const float4*)W)[f4];
        __half2* p = (__half2*)&Wh[r][c4 * 4];
        p[0] = __floats2half2_rn(v.x, v.y);
        p[1] = __floats2half2_rn(v.z, v.w);
    }

#pragma unroll
    for (int i = 0; i < 4; i++) {
        int idx = tid + i * 256;        // 0..1023
        int r   = idx >> 3;             // 0..127
        int q   = idx & 7;              // 8-half chunk
        int row = rowBase + r;
        uint4 v = make_uint4(0u, 0u, 0u, 0u);
        float di = 0.f;
        if (row < N_NODES) {
            v = ((const uint4*)in)[(size_t)row * 8 + q];
            di = g_dinv[row];
        }
        __half2 ph[4];
        float2 f0 = __half22float2(*(__half2*)&v.x);
        float2 f1 = __half22float2(*(__half2*)&v.y);
        float2 f2 = __half22float2(*(__half2*)&v.z);
        float2 f3 = __half22float2(*(__half2*)&v.w);
        ph[0] = __floats2half2_rn(f0.x * di, f0.y * di);
        ph[1] = __floats2half2_rn(f1.x * di, f1.y * di);
        ph[2] = __floats2half2_rn(f2.x * di, f2.y * di);
        ph[3] = __floats2half2_rn(f3.x * di, f3.y * di);
        *(uint4*)&Xh[r][q * 8] = *(uint4*)ph;
    }
    __syncthreads();

    const int w = tid >> 5;
    wmma::fragment<wmma::accumulator, 16, 16, 16, float> c[4];
#pragma unroll
    for (int cg = 0; cg < 4; cg++) wmma::fill_fragment(c[cg], 0.f);
#pragma unroll
    for (int k = 0; k < 4; k++) {
        wmma::fragment<wmma::matrix_a, 16, 16, 16, __half, wmma::row_major> a;
        wmma::load_matrix_sync(a, &Xh[w * 16][k * 16], 72);
#pragma unroll
        for (int cg = 0; cg < 4; cg++) {
            wmma::fragment<wmma::matrix_b, 16, 16, 16, __half, wmma::row_major> b;
            wmma::load_matrix_sync(b, &Wh[k * 16][cg * 16], 72);
            wmma::mma_sync(c[cg], a, b, c[cg]);
        }
    }
    __syncthreads();
#pragma unroll
    for (int cg = 0; cg < 4; cg++)
        wmma::store_matrix_sync(&Out[w * 16][cg * 16], c[cg], 68, wmma::mem_row_major);
    __syncthreads();

#pragma unroll
    for (int i = 0; i < 4; i++) {
        int idx = tid + i * 256;
        int r   = idx >> 3;
        int q   = idx & 7;
        int row = rowBase + r;
        if (row < N_NODES) {
            const float* src = &Out[r][q * 8];
            __half2 ph[4];
            ph[0] = __floats2half2_rn(src[0], src[1]);
            ph[1] = __floats2half2_rn(src[2], src[3]);
            ph[2] = __floats2half2_rn(src[4], src[5]);
            ph[3] = __floats2half2_rn(src[6], src[7]);
            ((uint4*)hs)[(size_t)row * 8 + q] = *(uint4*)ph;
        }
    }
}

// ---------------- fp16 accumulate helper: a[0..7] += unpack(v) ----------------
__device__ __forceinline__ void acc_u4(float* a, uint4 v) {
    float2 f0 = __half22float2(*(__half2*)&v.x);
    float2 f1 = __half22float2(*(__half2*)&v.y);
    float2 f2 = __half22float2(*(__half2*)&v.z);
    float2 f3 = __half22float2(*(__half2*)&v.w);
    a[0] += f0.x; a[1] += f0.y; a[2] += f1.x; a[3] += f1.y;
    a[4] += f2.x; a[5] += f2.y; a[6] += f3.x; a[7] += f3.y;
}

// ---------------- CSR gather: ha[n] = act( dinv[n]*(hs[n]+sum hs[s]) + bias ) fp16 ----------------
template<bool RELU_OUT>
__global__ __launch_bounds__(256) void k_gather(const __half* __restrict__ hs,
                                                const float* __restrict__ bias,
                                                __half* __restrict__ ha) {
    int t = blockIdx.x * blockDim.x + threadIdx.x;
    int node = t >> 3;
    int lane = t & 7;
    if (node >= N_NODES) return;

    const uint4* hs4 = (const uint4*)hs;
    int start = g_off[node] + g_boff[node >> 8];
    int cnt   = g_deg[node];

    float a[8] = {0.f, 0.f, 0.f, 0.f, 0.f, 0.f, 0.f, 0.f};
    float b[8] = {0.f, 0.f, 0.f, 0.f, 0.f, 0.f, 0.f, 0.f};

    acc_u4(a, hs4[(size_t)node * 8 + lane]);   // self term

    int i = 0;
    for (; i + 4 <= cnt; i += 4) {
        int s0 = g_csr[start + i + 0];
        int s1 = g_csr[start + i + 1];
        int s2 = g_csr[start + i + 2];
        int s3 = g_csr[start + i + 3];
        uint4 v0 = hs4[(size_t)s0 * 8 + lane];
        uint4 v1 = hs4[(size_t)s1 * 8 + lane];
        uint4 v2 = hs4[(size_t)s2 * 8 + lane];
        uint4 v3 = hs4[(size_t)s3 * 8 + lane];
        acc_u4(a, v0);
        acc_u4(b, v1);
        acc_u4(a, v2);
        acc_u4(b, v3);
    }
    for (; i < cnt; i++) {
        int s0 = g_csr[start + i];
        acc_u4(a, hs4[(size_t)s0 * 8 + lane]);
    }

    float dv = g_dinv[node];
    float4 bv0 = ((const float4*)bias)[lane * 2 + 0];
    float4 bv1 = ((const float4*)bias)[lane * 2 + 1];
    float o[8];
    o[0] = dv * (a[0] + b[0]) + bv0.x;
    o[1] = dv * (a[1] + b[1]) + bv0.y;
    o[2] = dv * (a[2] + b[2]) + bv0.z;
    o[3] = dv * (a[3] + b[3]) + bv0.w;
    o[4] = dv * (a[4] + b[4]) + bv1.x;
    o[5] = dv * (a[5] + b[5]) + bv1.y;
    o[6] = dv * (a[6] + b[6]) + bv1.z;
    o[7] = dv * (a[7] + b[7]) + bv1.w;
    if (RELU_OUT) {
#pragma unroll
        for (int j = 0; j < 8; j++) o[j] = fmaxf(o[j], 0.f);
    }
    __half2 ph[4];
    ph[0] = __floats2half2_rn(o[0], o[1]);
    ph[1] = __floats2half2_rn(o[2], o[3]);
    ph[2] = __floats2half2_rn(o[4], o[5]);
    ph[3] = __floats2half2_rn(o[6], o[7]);
    ((uint4*)ha)[(size_t)node * 8 + lane] = *(uint4*)ph;
}

// ---------------- fused mean-pool (batch is sorted) + MLP head ----------------
__global__ __launch_bounds__(64) void k_pool_head(const __half* __restrict__ ha,
                                                  const int* __restrict__ batch,
                                                  const float* __restrict__ lw1,
                                                  const float* __restrict__ lb1,
                                                  const float* __restrict__ lw2,
                                                  const float* __restrict__ lb2,
                                                  float* __restrict__ out) {
    int g = blockIdx.x;
    int tid = threadIdx.x;  // 64

    int l = 0, r = N_NODES;
    while (l < r) { int m = (l + r) >> 1; if (batch[m] < g) l = m + 1; else r = m; }
    int lo = l;
    r = N_NODES;
    while (l < r) { int m = (l + r) >> 1; if (batch[m] < g + 1) l = m + 1; else r = m; }
    int hi = l;

    float acc = 0.f;
    for (int n = lo; n < hi; n++) acc += __half2float(ha[(size_t)n * 64 + tid]);
    int cnt = hi - lo;
    float pooled = acc / (float)(cnt > 0 ? cnt : 1);

    __shared__ float sp[64];
    __shared__ float sz[32];
    sp[tid] = pooled;
    __syncthreads();

    if (tid < 32) {
        float z = lb1[tid];
#pragma unroll 8
        for (int k = 0; k < 64; k++) z += sp[k] * lw1[k * 32 + tid];
        sz[tid] = fmaxf(z, 0.f);
    }
    __syncthreads();

    if (tid < 8) {
        float o = lb2[tid];
#pragma unroll
        for (int j = 0; j < 32; j++) o += sz[j] * lw2[j * 8 + tid];
        out[g * 8 + tid] = o;
    }
}

// ---------------- launch ----------------
extern "C" void kernel_launch(void* const* d_in, const int* in_sizes, int n_in,
                              void* d_out, int out_size) {
    const float* x   = (const float*)d_in[0];
    const int*   ei  = (const int*)d_in[1];
    const int*   bat = (const int*)d_in[2];
    const float* W1  = (const float*)d_in[3];
    const float* b1  = (const float*)d_in[4];
    const float* W2  = (const float*)d_in[5];
    const float* b2  = (const float*)d_in[6];
    const float* lw1 = (const float*)d_in[7];
    const float* lb1 = (const float*)d_in[8];
    const float* lw2 = (const float*)d_in[9];
    const float* lb2 = (const float*)d_in[10];
    float* out = (float*)d_out;

    __half *hs, *ha;
    int *degp, *curp;
    cudaGetSymbolAddress((void**)&hs,   g_hs);
    cudaGetSymbolAddress((void**)&ha,   g_ha);
    cudaGetSymbolAddress((void**)&degp, g_deg);
    cudaGetSymbolAddress((void**)&curp, g_cursor);

    static cudaStream_t s2 = nullptr;
    static cudaEvent_t evFork = nullptr, evJoin = nullptr;
    if (s2 == nullptr) {
        cudaStreamCreateWithFlags(&s2, cudaStreamNonBlocking);
        cudaEventCreateWithFlags(&evFork, cudaEventDisableTiming);
        cudaEventCreateWithFlags(&evJoin, cudaEventDisableTiming);
    }

    const int nblk = (N_NODES + 255) / 256;
    const int eblk = (N_EDGES + 255) / 256;
    const int gemm_blocks = (N_NODES + 127) / 128;
    const int gath_blocks = (N_NODES * 8 + 255) / 256;
    const int scale_blocks = (N_NODES * 8 + 255) / 256;

    // fork immediately: ENTIRE CSR chain on s2 || GEMM1 (no dinv dep) on main
    cudaEventRecord(evFork, 0);
    cudaStreamWaitEvent(s2, evFork, 0);

    cudaMemsetAsync(degp, 0, N_NODES * sizeof(int), s2);
    cudaMemsetAsync(curp, 0, N_NODES * sizeof(int), s2);
    k_deg_count<<<(N_EDGES / 4 + 255) / 256, 256, 0, s2>>>(ei);
    k_dinv<<<nblk, 256, 0, s2>>>();
    k_scanA<<<NB_SCAN, 256, 0, s2>>>();
    k_scanB<<<1, 512, 0, s2>>>();
    k_fill<<<eblk, 256, 0, s2>>>(ei);

    k_gemm_l1<<<gemm_blocks, 256>>>(x, W1, hs);   // concurrent, unscaled

    cudaEventRecord(evJoin, s2);
    cudaStreamWaitEvent(0, evJoin, 0);

    // apply dinv row scale in place, then layer-1 aggregation
    k_scale<<<scale_blocks, 256>>>(hs);
    k_gather<true><<<gath_blocks, 256>>>(hs, b1, ha);

    // layer 2: fp16-input GEMM (dinv applied in staging), gather (no relu)
    k_gemm_l2<<<gemm_blocks, 256>>>(ha, W2, hs);
    k_gather<false><<<gath_blocks, 256>>>(hs, b2, ha);

    // pool per graph + MLP head
    k_pool_head<<<N_GRAPHS, 64>>>(ha, bat, lw1, lb1, lw2, lb2, out);
}

// round 12
// speedup vs baseline: 1.0254x; 1.0254x over previous
#include <cuda_runtime.h>
#include <cuda_fp16.h>
#include <mma.h>

using namespace nvcuda;

#define N_NODES  100000
#define N_EDGES  1600000
#define N_GRAPHS 1000
#define D        64

// ---------------- device scratch (no allocations allowed) ----------------
__device__ int    g_deg[N_NODES];           // in-degree (0-based; self-loop added at use)
__device__ int    g_off[N_NODES];           // CSR row offsets (absolute)
__device__ int    g_cursor[N_NODES];        // fill cursors (seeded to g_off by k_scan)
__device__ int    g_total;                  // running total for atomic block offsets
__device__ int    g_csr[N_EDGES];           // src indices grouped by dst
__device__ float  g_dinv[N_NODES];          // rsqrt(deg+1)
__device__ __half g_hs[(size_t)N_NODES * D];  // fp16 prescaled GEMM outputs
__device__ __half g_ha[(size_t)N_NODES * D];  // fp16 aggregation outputs

// ---------------- degree count (deg starts at 0 via memset) ----------------
__global__ void k_deg_count(const int* __restrict__ ei) {
    int t = blockIdx.x * blockDim.x + threadIdx.x;
    if (t < N_EDGES / 4) {
        int4 d = ((const int4*)(ei + N_EDGES))[t];
        atomicAdd(&g_deg[d.x], 1);
        atomicAdd(&g_deg[d.y], 1);
        atomicAdd(&g_deg[d.z], 1);
        atomicAdd(&g_deg[d.w], 1);
    }
}

// ---------------- fused scan: absolute CSR offsets + cursor seed + dinv ----------------
// Block-local exclusive scan; last thread grabs the block's absolute base via
// atomicAdd on g_total. Block ordering is non-deterministic, which only permutes
// where each node's CSR row lives (contents per node unchanged).
__global__ __launch_bounds__(256) void k_scan() {
    __shared__ int s[256];
    __shared__ int blockOff;
    int tid = threadIdx.x;
    int i = blockIdx.x * 256 + tid;
    int deg = (i < N_NODES) ? g_deg[i] : 0;
    s[tid] = deg;
    __syncthreads();
#pragma unroll
    for (int o = 1; o < 256; o <<= 1) {
        int t = (tid >= o) ? s[tid - o] : 0;
        __syncthreads();
        s[tid] += t;
        __syncthreads();
    }
    if (tid == 255) blockOff = atomicAdd(&g_total, s[255]);
    __syncthreads();
    if (i < N_NODES) {
        int a = blockOff + s[tid] - deg;   // absolute exclusive offset
        g_off[i] = a;
        g_cursor[i] = a;
        g_dinv[i] = rsqrtf((float)(deg + 1));
    }
}

// ---------------- CSR fill: 4 edges/thread, cursor returns absolute position ----------------
__global__ __launch_bounds__(256) void k_fill(const int* __restrict__ ei) {
    int t = blockIdx.x * blockDim.x + threadIdx.x;
    if (t < N_EDGES / 4) {
        int4 s4 = ((const int4*)ei)[t];
        int4 d4 = ((const int4*)(ei + N_EDGES))[t];
        g_csr[atomicAdd(&g_cursor[d4.x], 1)] = s4.x;
        g_csr[atomicAdd(&g_cursor[d4.y], 1)] = s4.y;
        g_csr[atomicAdd(&g_cursor[d4.z], 1)] = s4.z;
        g_csr[atomicAdd(&g_cursor[d4.w], 1)] = s4.w;
    }
}

// ---------------- GEMM layer 1: hs = fp16( (x*dinv[row]) @ W1 ), x fp32 ----------------
__global__ __launch_bounds__(256) void k_gemm_l1(const float* __restrict__ in,
                                                 const float* __restrict__ W,
                                                 __half* __restrict__ hs) {
    __shared__ __align__(16) char smem_raw[128 * 68 * 4];
    __half (*Xh)[72] = (__half(*)[72])smem_raw;
    __half (*Wh)[72] = (__half(*)[72])(smem_raw + 18432);
    float  (*Out)[68] = (float(*)[68])smem_raw;

    const int tid = threadIdx.x;
    const int rowBase = blockIdx.x * 128;

#pragma unroll
    for (int i = 0; i < 4; i++) {
        int f4 = tid + i * 256;
        int r  = f4 >> 4;
        int c4 = f4 & 15;
        float4 v = ((const float4*)W)[f4];
        __half2* p = (__half2*)&Wh[r][c4 * 4];
        p[0] = __floats2half2_rn(v.x, v.y);
        p[1] = __floats2half2_rn(v.z, v.w);
    }

#pragma unroll
    for (int i = 0; i < 8; i++) {
        int f4  = tid + i * 256;
        int r   = f4 >> 4;
        int c4  = f4 & 15;
        int row = rowBase + r;
        float4 v = make_float4(0.f, 0.f, 0.f, 0.f);
        float di = 0.f;
        if (row < N_NODES) {
            v = ((const float4*)in)[(size_t)row * 16 + c4];
            di = g_dinv[row];
        }
        __half2* p = (__half2*)&Xh[r][c4 * 4];
        p[0] = __floats2half2_rn(v.x * di, v.y * di);
        p[1] = __floats2half2_rn(v.z * di, v.w * di);
    }
    __syncthreads();

    const int w = tid >> 5;
    wmma::fragment<wmma::accumulator, 16, 16, 16, float> c[4];
#pragma unroll
    for (int cg = 0; cg < 4; cg++) wmma::fill_fragment(c[cg], 0.f);
#pragma unroll
    for (int k = 0; k < 4; k++) {
        wmma::fragment<wmma::matrix_a, 16, 16, 16, __half, wmma::row_major> a;
        wmma::load_matrix_sync(a, &Xh[w * 16][k * 16], 72);
#pragma unroll
        for (int cg = 0; cg < 4; cg++) {
            wmma::fragment<wmma::matrix_b, 16, 16, 16, __half, wmma::row_major> b;
            wmma::load_matrix_sync(b, &Wh[k * 16][cg * 16], 72);
            wmma::mma_sync(c[cg], a, b, c[cg]);
        }
    }
    __syncthreads();
#pragma unroll
    for (int cg = 0; cg < 4; cg++)
        wmma::store_matrix_sync(&Out[w * 16][cg * 16], c[cg], 68, wmma::mem_row_major);
    __syncthreads();

#pragma unroll
    for (int i = 0; i < 4; i++) {
        int idx = tid + i * 256;
        int r   = idx >> 3;
        int q   = idx & 7;
        int row = rowBase + r;
        if (row < N_NODES) {
            const float* src = &Out[r][q * 8];
            __half2 ph[4];
            ph[0] = __floats2half2_rn(src[0], src[1]);
            ph[1] = __floats2half2_rn(src[2], src[3]);
            ph[2] = __floats2half2_rn(src[4], src[5]);
            ph[3] = __floats2half2_rn(src[6], src[7]);
            ((uint4*)hs)[(size_t)row * 8 + q] = *(uint4*)ph;
        }
    }
}

// ---------------- GEMM layer 2: hs = fp16( (ha*dinv[row]) @ W2 ), ha fp16 ----------------
__global__ __launch_bounds__(256) void k_gemm_l2(const __half* __restrict__ in,
                                                 const float* __restrict__ W,
                                                 __half* __restrict__ hs) {
    __shared__ __align__(16) char smem_raw[128 * 68 * 4];
    __half (*Xh)[72] = (__half(*)[72])smem_raw;
    __half (*Wh)[72] = (__half(*)[72])(smem_raw + 18432);
    float  (*Out)[68] = (float(*)[68])smem_raw;

    const int tid = threadIdx.x;
    const int rowBase = blockIdx.x * 128;

#pragma unroll
    for (int i = 0; i < 4; i++) {
        int f4 = tid + i * 256;
        int r  = f4 >> 4;
        int c4 = f4 & 15;
        float4 v = ((const float4*)W)[f4];
        __half2* p = (__half2*)&Wh[r][c4 * 4];
        p[0] = __floats2half2_rn(v.x, v.y);
        p[1] = __floats2half2_rn(v.z, v.w);
    }

#pragma unroll
    for (int i = 0; i < 4; i++) {
        int idx = tid + i * 256;        // 0..1023
        int r   = idx >> 3;             // 0..127
        int q   = idx & 7;              // 8-half chunk
        int row = rowBase + r;
        uint4 v = make_uint4(0u, 0u, 0u, 0u);
        float di = 0.f;
        if (row < N_NODES) {
            v = ((const uint4*)in)[(size_t)row * 8 + q];
            di = g_dinv[row];
        }
        __half2 ph[4];
        float2 f0 = __half22float2(*(__half2*)&v.x);
        float2 f1 = __half22float2(*(__half2*)&v.y);
        float2 f2 = __half22float2(*(__half2*)&v.z);
        float2 f3 = __half22float2(*(__half2*)&v.w);
        ph[0] = __floats2half2_rn(f0.x * di, f0.y * di);
        ph[1] = __floats2half2_rn(f1.x * di, f1.y * di);
        ph[2] = __floats2half2_rn(f2.x * di, f2.y * di);
        ph[3] = __floats2half2_rn(f3.x * di, f3.y * di);
        *(uint4*)&Xh[r][q * 8] = *(uint4*)ph;
    }
    __syncthreads();

    const int w = tid >> 5;
    wmma::fragment<wmma::accumulator, 16, 16, 16, float> c[4];
#pragma unroll
    for (int cg = 0; cg < 4; cg++) wmma::fill_fragment(c[cg], 0.f);
#pragma unroll
    for (int k = 0; k < 4; k++) {
        wmma::fragment<wmma::matrix_a, 16, 16, 16, __half, wmma::row_major> a;
        wmma::load_matrix_sync(a, &Xh[w * 16][k * 16], 72);
#pragma unroll
        for (int cg = 0; cg < 4; cg++) {
            wmma::fragment<wmma::matrix_b, 16, 16, 16, __half, wmma::row_major> b;
            wmma::load_matrix_sync(b, &Wh[k * 16][cg * 16], 72);
            wmma::mma_sync(c[cg], a, b, c[cg]);
        }
    }
    __syncthreads();
#pragma unroll
    for (int cg = 0; cg < 4; cg++)
        wmma::store_matrix_sync(&Out[w * 16][cg * 16], c[cg], 68, wmma::mem_row_major);
    __syncthreads();

#pragma unroll
    for (int i = 0; i < 4; i++) {
        int idx = tid + i * 256;
        int r   = idx >> 3;
        int q   = idx & 7;
        int row = rowBase + r;
        if (row < N_NODES) {
            const float* src = &Out[r][q * 8];
            __half2 ph[4];
            ph[0] = __floats2half2_rn(src[0], src[1]);
            ph[1] = __floats2half2_rn(src[2], src[3]);
            ph[2] = __floats2half2_rn(src[4], src[5]);
            ph[3] = __floats2half2_rn(src[6], src[7]);
            ((uint4*)hs)[(size_t)row * 8 + q] = *(uint4*)ph;
        }
    }
}

// ---------------- fp16 accumulate helper: a[0..7] += unpack(v) ----------------
__device__ __forceinline__ void acc_u4(float* a, uint4 v) {
    float2 f0 = __half22float2(*(__half2*)&v.x);
    float2 f1 = __half22float2(*(__half2*)&v.y);
    float2 f2 = __half22float2(*(__half2*)&v.z);
    float2 f3 = __half22float2(*(__half2*)&v.w);
    a[0] += f0.x; a[1] += f0.y; a[2] += f1.x; a[3] += f1.y;
    a[4] += f2.x; a[5] += f2.y; a[6] += f3.x; a[7] += f3.y;
}

// ---------------- CSR gather: ha[n] = act( dinv[n]*(hs[n]+sum hs[s]) + bias ) fp16 ----------------
template<bool RELU_OUT>
__global__ __launch_bounds__(256) void k_gather(const __half* __restrict__ hs,
                                                const float* __restrict__ bias,
                                                __half* __restrict__ ha) {
    int t = blockIdx.x * blockDim.x + threadIdx.x;
    int node = t >> 3;
    int lane = t & 7;
    if (node >= N_NODES) return;

    const uint4* hs4 = (const uint4*)hs;
    int start = g_off[node];
    int cnt   = g_deg[node];

    float a[8] = {0.f, 0.f, 0.f, 0.f, 0.f, 0.f, 0.f, 0.f};
    float b[8] = {0.f, 0.f, 0.f, 0.f, 0.f, 0.f, 0.f, 0.f};

    acc_u4(a, hs4[(size_t)node * 8 + lane]);   // self term

    int i = 0;
    for (; i + 4 <= cnt; i += 4) {
        int s0 = g_csr[start + i + 0];
        int s1 = g_csr[start + i + 1];
        int s2 = g_csr[start + i + 2];
        int s3 = g_csr[start + i + 3];
        uint4 v0 = hs4[(size_t)s0 * 8 + lane];
        uint4 v1 = hs4[(size_t)s1 * 8 + lane];
        uint4 v2 = hs4[(size_t)s2 * 8 + lane];
        uint4 v3 = hs4[(size_t)s3 * 8 + lane];
        acc_u4(a, v0);
        acc_u4(b, v1);
        acc_u4(a, v2);
        acc_u4(b, v3);
    }
    for (; i < cnt; i++) {
        int s0 = g_csr[start + i];
        acc_u4(a, hs4[(size_t)s0 * 8 + lane]);
    }

    float dv = g_dinv[node];
    float4 bv0 = ((const float4*)bias)[lane * 2 + 0];
    float4 bv1 = ((const float4*)bias)[lane * 2 + 1];
    float o[8];
    o[0] = dv * (a[0] + b[0]) + bv0.x;
    o[1] = dv * (a[1] + b[1]) + bv0.y;
    o[2] = dv * (a[2] + b[2]) + bv0.z;
    o[3] = dv * (a[3] + b[3]) + bv0.w;
    o[4] = dv * (a[4] + b[4]) + bv1.x;
    o[5] = dv * (a[5] + b[5]) + bv1.y;
    o[6] = dv * (a[6] + b[6]) + bv1.z;
    o[7] = dv * (a[7] + b[7]) + bv1.w;
    if (RELU_OUT) {
#pragma unroll
        for (int j = 0; j < 8; j++) o[j] = fmaxf(o[j], 0.f);
    }
    __half2 ph[4];
    ph[0] = __floats2half2_rn(o[0], o[1]);
    ph[1] = __floats2half2_rn(o[2], o[3]);
    ph[2] = __floats2half2_rn(o[4], o[5]);
    ph[3] = __floats2half2_rn(o[6], o[7]);
    ((uint4*)ha)[(size_t)node * 8 + lane] = *(uint4*)ph;
}

// ---------------- fused mean-pool (batch is sorted) + MLP head ----------------
__global__ __launch_bounds__(64) void k_pool_head(const __half* __restrict__ ha,
                                                  const int* __restrict__ batch,
                                                  const float* __restrict__ lw1,
                                                  const float* __restrict__ lb1,
                                                  const float* __restrict__ lw2,
                                                  const float* __restrict__ lb2,
                                                  float* __restrict__ out) {
    int g = blockIdx.x;
    int tid = threadIdx.x;  // 64

    int l = 0, r = N_NODES;
    while (l < r) { int m = (l + r) >> 1; if (batch[m] < g) l = m + 1; else r = m; }
    int lo = l;
    r = N_NODES;
    while (l < r) { int m = (l + r) >> 1; if (batch[m] < g + 1) l = m + 1; else r = m; }
    int hi = l;

    float acc = 0.f;
    for (int n = lo; n < hi; n++) acc += __half2float(ha[(size_t)n * 64 + tid]);
    int cnt = hi - lo;
    float pooled = acc / (float)(cnt > 0 ? cnt : 1);

    __shared__ float sp[64];
    __shared__ float sz[32];
    sp[tid] = pooled;
    __syncthreads();

    if (tid < 32) {
        float z = lb1[tid];
#pragma unroll 8
        for (int k = 0; k < 64; k++) z += sp[k] * lw1[k * 32 + tid];
        sz[tid] = fmaxf(z, 0.f);
    }
    __syncthreads();

    if (tid < 8) {
        float o = lb2[tid];
#pragma unroll
        for (int j = 0; j < 32; j++) o += sz[j] * lw2[j * 8 + tid];
        out[g * 8 + tid] = o;
    }
}

// ---------------- launch ----------------
extern "C" void kernel_launch(void* const* d_in, const int* in_sizes, int n_in,
                              void* d_out, int out_size) {
    const float* x   = (const float*)d_in[0];
    const int*   ei  = (const int*)d_in[1];
    const int*   bat = (const int*)d_in[2];
    const float* W1  = (const float*)d_in[3];
    const float* b1  = (const float*)d_in[4];
    const float* W2  = (const float*)d_in[5];
    const float* b2  = (const float*)d_in[6];
    const float* lw1 = (const float*)d_in[7];
    const float* lb1 = (const float*)d_in[8];
    const float* lw2 = (const float*)d_in[9];
    const float* lb2 = (const float*)d_in[10];
    float* out = (float*)d_out;

    __half *hs, *ha;
    int *degp, *totp;
    cudaGetSymbolAddress((void**)&hs,   g_hs);
    cudaGetSymbolAddress((void**)&ha,   g_ha);
    cudaGetSymbolAddress((void**)&degp, g_deg);
    cudaGetSymbolAddress((void**)&totp, g_total);

    static cudaStream_t s2 = nullptr;
    static cudaEvent_t evFork = nullptr, evJoin = nullptr;
    if (s2 == nullptr) {
        cudaStreamCreateWithFlags(&s2, cudaStreamNonBlocking);
        cudaEventCreateWithFlags(&evFork, cudaEventDisableTiming);
        cudaEventCreateWithFlags(&evJoin, cudaEventDisableTiming);
    }

    const int nblk = (N_NODES + 255) / 256;
    const int gemm_blocks = (N_NODES + 127) / 128;
    const int gath_blocks = (N_NODES * 8 + 255) / 256;
    const int e4blk = (N_EDGES / 4 + 255) / 256;

    // serial prefix on main: zero deg/total, count degrees, fused scan(+cursor+dinv)
    cudaMemsetAsync(degp, 0, N_NODES * sizeof(int), 0);
    cudaMemsetAsync(totp, 0, sizeof(int), 0);
    k_deg_count<<<e4blk, 256>>>(ei);
    k_scan<<<nblk, 256>>>();

    // fork: fill on s2 || GEMM1 on main (balanced ~10-12us each)
    cudaEventRecord(evFork, 0);
    cudaStreamWaitEvent(s2, evFork, 0);

    k_fill<<<e4blk, 256, 0, s2>>>(ei);

    k_gemm_l1<<<gemm_blocks, 256>>>(x, W1, hs);   // concurrent

    cudaEventRecord(evJoin, s2);
    cudaStreamWaitEvent(0, evJoin, 0);

    // layer 1 aggregation: ha = relu(dinv*(sum)+b1) in fp16
    k_gather<true><<<gath_blocks, 256>>>(hs, b1, ha);

    // layer 2: fp16-input GEMM (dinv applied in staging), gather (no relu)
    k_gemm_l2<<<gemm_blocks, 256>>>(ha, W2, hs);
    k_gather<false><<<gath_blocks, 256>>>(hs, b2, ha);

    // pool per graph + MLP head
    k_pool_head<<<N_GRAPHS, 64>>>(ha, bat, lw1, lb1, lw2, lb2, out);
}

// round 13
// speedup vs baseline: 1.1377x; 1.1096x over previous
#include <cuda_runtime.h>
#include <cuda_fp16.h>
#include <mma.h>

using namespace nvcuda;

#define N_NODES  100000
#define N_EDGES  1600000
#define N_GRAPHS 1000
#define D        64

// ---------------- device scratch (no allocations allowed) ----------------
__device__ int    g_deg[N_NODES];           // in-degree (0-based; self-loop added at use)
__device__ int    g_off[N_NODES];           // CSR row offsets (absolute)
__device__ int    g_cursor[N_NODES];        // fill cursors (seeded to g_off by k_scan)
__device__ int    g_total;                  // running total for atomic block offsets
__device__ int    g_csr[N_EDGES];           // src indices grouped by dst
__device__ float  g_dinv[N_NODES];          // rsqrt(deg+1)
__device__ __half g_hs[(size_t)N_NODES * D];  // fp16 prescaled GEMM outputs
__device__ __half g_ha[(size_t)N_NODES * D];  // fp16 aggregation outputs

// ---------------- degree count (deg starts at 0 via memset) ----------------
__global__ void k_deg_count(const int* __restrict__ ei) {
    int t = blockIdx.x * blockDim.x + threadIdx.x;
    if (t < N_EDGES / 4) {
        int4 d = ((const int4*)(ei + N_EDGES))[t];
        atomicAdd(&g_deg[d.x], 1);
        atomicAdd(&g_deg[d.y], 1);
        atomicAdd(&g_deg[d.z], 1);
        atomicAdd(&g_deg[d.w], 1);
    }
}

// ---------------- fused scan: absolute CSR offsets + cursor seed + dinv ----------------
__global__ __launch_bounds__(256) void k_scan() {
    __shared__ int s[256];
    __shared__ int blockOff;
    int tid = threadIdx.x;
    int i = blockIdx.x * 256 + tid;
    int deg = (i < N_NODES) ? g_deg[i] : 0;
    s[tid] = deg;
    __syncthreads();
#pragma unroll
    for (int o = 1; o < 256; o <<= 1) {
        int t = (tid >= o) ? s[tid - o] : 0;
        __syncthreads();
        s[tid] += t;
        __syncthreads();
    }
    if (tid == 255) blockOff = atomicAdd(&g_total, s[255]);
    __syncthreads();
    if (i < N_NODES) {
        int a = blockOff + s[tid] - deg;   // absolute exclusive offset
        g_off[i] = a;
        g_cursor[i] = a;
        g_dinv[i] = rsqrtf((float)(deg + 1));
    }
}

// ---------------- CSR fill: 4 edges/thread, cursor returns absolute position ----------------
__global__ __launch_bounds__(256) void k_fill(const int* __restrict__ ei) {
    int t = blockIdx.x * blockDim.x + threadIdx.x;
    if (t < N_EDGES / 4) {
        int4 s4 = ((const int4*)ei)[t];
        int4 d4 = ((const int4*)(ei + N_EDGES))[t];
        g_csr[atomicAdd(&g_cursor[d4.x], 1)] = s4.x;
        g_csr[atomicAdd(&g_cursor[d4.y], 1)] = s4.y;
        g_csr[atomicAdd(&g_cursor[d4.z], 1)] = s4.z;
        g_csr[atomicAdd(&g_cursor[d4.w], 1)] = s4.w;
    }
}

// ---------------- GEMM layer 1: hs = fp16( (x*dinv[row]) @ W1 ), x fp32 ----------------
__global__ __launch_bounds__(256) void k_gemm_l1(const float* __restrict__ in,
                                                 const float* __restrict__ W,
                                                 __half* __restrict__ hs) {
    __shared__ __align__(16) char smem_raw[128 * 68 * 4];
    __half (*Xh)[72] = (__half(*)[72])smem_raw;
    __half (*Wh)[72] = (__half(*)[72])(smem_raw + 18432);
    float  (*Out)[68] = (float(*)[68])smem_raw;

    const int tid = threadIdx.x;
    const int rowBase = blockIdx.x * 128;

#pragma unroll
    for (int i = 0; i < 4; i++) {
        int f4 = tid + i * 256;
        int r  = f4 >> 4;
        int c4 = f4 & 15;
        float4 v = ((const float4*)W)[f4];
        __half2* p = (__half2*)&Wh[r][c4 * 4];
        p[0] = __floats2half2_rn(v.x, v.y);
        p[1] = __floats2half2_rn(v.z, v.w);
    }

#pragma unroll
    for (int i = 0; i < 8; i++) {
        int f4  = tid + i * 256;
        int r   = f4 >> 4;
        int c4  = f4 & 15;
        int row = rowBase + r;
        float4 v = make_float4(0.f, 0.f, 0.f, 0.f);
        float di = 0.f;
        if (row < N_NODES) {
            v = ((const float4*)in)[(size_t)row * 16 + c4];
            di = g_dinv[row];
        }
        __half2* p = (__half2*)&Xh[r][c4 * 4];
        p[0] = __floats2half2_rn(v.x * di, v.y * di);
        p[1] = __floats2half2_rn(v.z * di, v.w * di);
    }
    __syncthreads();

    const int w = tid >> 5;
    wmma::fragment<wmma::accumulator, 16, 16, 16, float> c[4];
#pragma unroll
    for (int cg = 0; cg < 4; cg++) wmma::fill_fragment(c[cg], 0.f);
#pragma unroll
    for (int k = 0; k < 4; k++) {
        wmma::fragment<wmma::matrix_a, 16, 16, 16, __half, wmma::row_major> a;
        wmma::load_matrix_sync(a, &Xh[w * 16][k * 16], 72);
#pragma unroll
        for (int cg = 0; cg < 4; cg++) {
            wmma::fragment<wmma::matrix_b, 16, 16, 16, __half, wmma::row_major> b;
            wmma::load_matrix_sync(b, &Wh[k * 16][cg * 16], 72);
            wmma::mma_sync(c[cg], a, b, c[cg]);
        }
    }
    __syncthreads();
#pragma unroll
    for (int cg = 0; cg < 4; cg++)
        wmma::store_matrix_sync(&Out[w * 16][cg * 16], c[cg], 68, wmma::mem_row_major);
    __syncthreads();

#pragma unroll
    for (int i = 0; i < 4; i++) {
        int idx = tid + i * 256;
        int r   = idx >> 3;
        int q   = idx & 7;
        int row = rowBase + r;
        if (row < N_NODES) {
            const float* src = &Out[r][q * 8];
            __half2 ph[4];
            ph[0] = __floats2half2_rn(src[0], src[1]);
            ph[1] = __floats2half2_rn(src[2], src[3]);
            ph[2] = __floats2half2_rn(src[4], src[5]);
            ph[3] = __floats2half2_rn(src[6], src[7]);
            ((uint4*)hs)[(size_t)row * 8 + q] = *(uint4*)ph;
        }
    }
}

// ---------------- GEMM layer 2: hs = fp16( (ha*dinv[row]) @ W2 ), ha fp16 ----------------
__global__ __launch_bounds__(256) void k_gemm_l2(const __half* __restrict__ in,
                                                 const float* __restrict__ W,
                                                 __half* __restrict__ hs) {
    __shared__ __align__(16) char smem_raw[128 * 68 * 4];
    __half (*Xh)[72] = (__half(*)[72])smem_raw;
    __half (*Wh)[72] = (__half(*)[72])(smem_raw + 18432);
    float  (*Out)[68] = (float(*)[68])smem_raw;

    const int tid = threadIdx.x;
    const int rowBase = blockIdx.x * 128;

#pragma unroll
    for (int i = 0; i < 4; i++) {
        int f4 = tid + i * 256;
        int r  = f4 >> 4;
        int c4 = f4 & 15;
        float4 v = ((const float4*)W)[f4];
        __half2* p = (__half2*)&Wh[r][c4 * 4];
        p[0] = __floats2half2_rn(v.x, v.y);
        p[1] = __floats2half2_rn(v.z, v.w);
    }

#pragma unroll
    for (int i = 0; i < 4; i++) {
        int idx = tid + i * 256;        // 0..1023
        int r   = idx >> 3;             // 0..127
        int q   = idx & 7;              // 8-half chunk
        int row = rowBase + r;
        uint4 v = make_uint4(0u, 0u, 0u, 0u);
        float di = 0.f;
        if (row < N_NODES) {
            v = ((const uint4*)in)[(size_t)row * 8 + q];
            di = g_dinv[row];
        }
        __half2 ph[4];
        float2 f0 = __half22float2(*(__half2*)&v.x);
        float2 f1 = __half22float2(*(__half2*)&v.y);
        float2 f2 = __half22float2(*(__half2*)&v.z);
        float2 f3 = __half22float2(*(__half2*)&v.w);
        ph[0] = __floats2half2_rn(f0.x * di, f0.y * di);
        ph[1] = __floats2half2_rn(f1.x * di, f1.y * di);
        ph[2] = __floats2half2_rn(f2.x * di, f2.y * di);
        ph[3] = __floats2half2_rn(f3.x * di, f3.y * di);
        *(uint4*)&Xh[r][q * 8] = *(uint4*)ph;
    }
    __syncthreads();

    const int w = tid >> 5;
    wmma::fragment<wmma::accumulator, 16, 16, 16, float> c[4];
#pragma unroll
    for (int cg = 0; cg < 4; cg++) wmma::fill_fragment(c[cg], 0.f);
#pragma unroll
    for (int k = 0; k < 4; k++) {
        wmma::fragment<wmma::matrix_a, 16, 16, 16, __half, wmma::row_major> a;
        wmma::load_matrix_sync(a, &Xh[w * 16][k * 16], 72);
#pragma unroll
        for (int cg = 0; cg < 4; cg++) {
            wmma::fragment<wmma::matrix_b, 16, 16, 16, __half, wmma::row_major> b;
            wmma::load_matrix_sync(b, &Wh[k * 16][cg * 16], 72);
            wmma::mma_sync(c[cg], a, b, c[cg]);
        }
    }
    __syncthreads();
#pragma unroll
    for (int cg = 0; cg < 4; cg++)
        wmma::store_matrix_sync(&Out[w * 16][cg * 16], c[cg], 68, wmma::mem_row_major);
    __syncthreads();

#pragma unroll
    for (int i = 0; i < 4; i++) {
        int idx = tid + i * 256;
        int r   = idx >> 3;
        int q   = idx & 7;
        int row = rowBase + r;
        if (row < N_NODES) {
            const float* src = &Out[r][q * 8];
            __half2 ph[4];
            ph[0] = __floats2half2_rn(src[0], src[1]);
            ph[1] = __floats2half2_rn(src[2], src[3]);
            ph[2] = __floats2half2_rn(src[4], src[5]);
            ph[3] = __floats2half2_rn(src[6], src[7]);
            ((uint4*)hs)[(size_t)row * 8 + q] = *(uint4*)ph;
        }
    }
}

// ---------------- fp16 accumulate helpers ----------------
__device__ __forceinline__ void acc_u4(float* a, uint4 v) {
    float2 f0 = __half22float2(*(__half2*)&v.x);
    float2 f1 = __half22float2(*(__half2*)&v.y);
    float2 f2 = __half22float2(*(__half2*)&v.z);
    float2 f3 = __half22float2(*(__half2*)&v.w);
    a[0] += f0.x; a[1] += f0.y; a[2] += f1.x; a[3] += f1.y;
    a[4] += f2.x; a[5] += f2.y; a[6] += f3.x; a[7] += f3.y;
}

// 4 packed HADD2: a += v (element-wise fp16)
__device__ __forceinline__ uint4 hadd2_u4(uint4 a, uint4 v) {
    __half2* pa = (__half2*)&a;
    __half2* pv = (__half2*)&v;
    pa[0] = __hadd2(pa[0], pv[0]);
    pa[1] = __hadd2(pa[1], pv[1]);
    pa[2] = __hadd2(pa[2], pv[2]);
    pa[3] = __hadd2(pa[3], pv[3]);
    return a;
}

// ---------------- CSR gather: ha[n] = act( dinv[n]*(hs[n]+sum hs[s]) + bias ) fp16 ----------------
// 8 lanes/node. Inner loop sums groups of 4 edges with a 2-level fp16 HADD2 tree
// (12 HADD2 + one fp32 convert-add per group) -> ~2.3x fewer ALU ops than per-edge
// fp32 conversion. Remainder edges + self term use the exact fp32 path.
template<bool RELU_OUT>
__global__ __launch_bounds__(256) void k_gather(const __half* __restrict__ hs,
                                                const float* __restrict__ bias,
                                                __half* __restrict__ ha) {
    int t = blockIdx.x * blockDim.x + threadIdx.x;
    int node = t >> 3;
    int lane = t & 7;
    if (node >= N_NODES) return;

    const uint4* hs4 = (const uint4*)hs;
    int start = g_off[node];
    int cnt   = g_deg[node];

    float a[8] = {0.f, 0.f, 0.f, 0.f, 0.f, 0.f, 0.f, 0.f};

    acc_u4(a, hs4[(size_t)node * 8 + lane]);   // self term (fp32 exact)

    int i = 0;
    for (; i + 4 <= cnt; i += 4) {
        int s0 = g_csr[start + i + 0];
        int s1 = g_csr[start + i + 1];
        int s2 = g_csr[start + i + 2];
        int s3 = g_csr[start + i + 3];
        uint4 v0 = hs4[(size_t)s0 * 8 + lane];
        uint4 v1 = hs4[(size_t)s1 * 8 + lane];
        uint4 v2 = hs4[(size_t)s2 * 8 + lane];
        uint4 v3 = hs4[(size_t)s3 * 8 + lane];
        // 2-level fp16 tree: (v0+v1) + (v2+v3), then one fp32 convert-add
        uint4 p01 = hadd2_u4(v0, v1);
        uint4 p23 = hadd2_u4(v2, v3);
        uint4 q   = hadd2_u4(p01, p23);
        acc_u4(a, q);
    }
    for (; i < cnt; i++) {
        int s0 = g_csr[start + i];
        acc_u4(a, hs4[(size_t)s0 * 8 + lane]);
    }

    float dv = g_dinv[node];
    float4 bv0 = ((const float4*)bias)[lane * 2 + 0];
    float4 bv1 = ((const float4*)bias)[lane * 2 + 1];
    float o[8];
    o[0] = dv * a[0] + bv0.x;
    o[1] = dv * a[1] + bv0.y;
    o[2] = dv * a[2] + bv0.z;
    o[3] = dv * a[3] + bv0.w;
    o[4] = dv * a[4] + bv1.x;
    o[5] = dv * a[5] + bv1.y;
    o[6] = dv * a[6] + bv1.z;
    o[7] = dv * a[7] + bv1.w;
    if (RELU_OUT) {
#pragma unroll
        for (int j = 0; j < 8; j++) o[j] = fmaxf(o[j], 0.f);
    }
    __half2 ph[4];
    ph[0] = __floats2half2_rn(o[0], o[1]);
    ph[1] = __floats2half2_rn(o[2], o[3]);
    ph[2] = __floats2half2_rn(o[4], o[5]);
    ph[3] = __floats2half2_rn(o[6], o[7]);
    ((uint4*)ha)[(size_t)node * 8 + lane] = *(uint4*)ph;
}

// ---------------- fused mean-pool (batch is sorted) + MLP head ----------------
__global__ __launch_bounds__(64) void k_pool_head(const __half* __restrict__ ha,
                                                  const int* __restrict__ batch,
                                                  const float* __restrict__ lw1,
                                                  const float* __restrict__ lb1,
                                                  const float* __restrict__ lw2,
                                                  const float* __restrict__ lb2,
                                                  float* __restrict__ out) {
    int g = blockIdx.x;
    int tid = threadIdx.x;  // 64

    int l = 0, r = N_NODES;
    while (l < r) { int m = (l + r) >> 1; if (batch[m] < g) l = m + 1; else r = m; }
    int lo = l;
    r = N_NODES;
    while (l < r) { int m = (l + r) >> 1; if (batch[m] < g + 1) l = m + 1; else r = m; }
    int hi = l;

    float acc = 0.f;
    for (int n = lo; n < hi; n++) acc += __half2float(ha[(size_t)n * 64 + tid]);
    int cnt = hi - lo;
    float pooled = acc / (float)(cnt > 0 ? cnt : 1);

    __shared__ float sp[64];
    __shared__ float sz[32];
    sp[tid] = pooled;
    __syncthreads();

    if (tid < 32) {
        float z = lb1[tid];
#pragma unroll 8
        for (int k = 0; k < 64; k++) z += sp[k] * lw1[k * 32 + tid];
        sz[tid] = fmaxf(z, 0.f);
    }
    __syncthreads();

    if (tid < 8) {
        float o = lb2[tid];
#pragma unroll
        for (int j = 0; j < 32; j++) o += sz[j] * lw2[j * 8 + tid];
        out[g * 8 + tid] = o;
    }
}

// ---------------- launch ----------------
extern "C" void kernel_launch(void* const* d_in, const int* in_sizes, int n_in,
                              void* d_out, int out_size) {
    const float* x   = (const float*)d_in[0];
    const int*   ei  = (const int*)d_in[1];
    const int*   bat = (const int*)d_in[2];
    const float* W1  = (const float*)d_in[3];
    const float* b1  = (const float*)d_in[4];
    const float* W2  = (const float*)d_in[5];
    const float* b2  = (const float*)d_in[6];
    const float* lw1 = (const float*)d_in[7];
    const float* lb1 = (const float*)d_in[8];
    const float* lw2 = (const float*)d_in[9];
    const float* lb2 = (const float*)d_in[10];
    float* out = (float*)d_out;

    __half *hs, *ha;
    int *degp, *totp;
    cudaGetSymbolAddress((void**)&hs,   g_hs);
    cudaGetSymbolAddress((void**)&ha,   g_ha);
    cudaGetSymbolAddress((void**)&degp, g_deg);
    cudaGetSymbolAddress((void**)&totp, g_total);

    static cudaStream_t s2 = nullptr;
    static cudaEvent_t evFork = nullptr, evJoin = nullptr;
    if (s2 == nullptr) {
        cudaStreamCreateWithFlags(&s2, cudaStreamNonBlocking);
        cudaEventCreateWithFlags(&evFork, cudaEventDisableTiming);
        cudaEventCreateWithFlags(&evJoin, cudaEventDisableTiming);
    }

    const int nblk = (N_NODES + 255) / 256;
    const int gemm_blocks = (N_NODES + 127) / 128;
    const int gath_blocks = (N_NODES * 8 + 255) / 256;
    const int e4blk = (N_EDGES / 4 + 255) / 256;

    // serial prefix on main: zero deg/total, count degrees, fused scan(+cursor+dinv)
    cudaMemsetAsync(degp, 0, N_NODES * sizeof(int), 0);
    cudaMemsetAsync(totp, 0, sizeof(int), 0);
    k_deg_count<<<e4blk, 256>>>(ei);
    k_scan<<<nblk, 256>>>();

    // fork: fill on s2 || GEMM1 on main (balanced ~10-15us each)
    cudaEventRecord(evFork, 0);
    cudaStreamWaitEvent(s2, evFork, 0);

    k_fill<<<e4blk, 256, 0, s2>>>(ei);

    k_gemm_l1<<<gemm_blocks, 256>>>(x, W1, hs);   // concurrent

    cudaEventRecord(evJoin, s2);
    cudaStreamWaitEvent(0, evJoin, 0);

    // layer 1 aggregation: ha = relu(dinv*(sum)+b1) in fp16
    k_gather<true><<<gath_blocks, 256>>>(hs, b1, ha);

    // layer 2: fp16-input GEMM (dinv applied in staging), gather (no relu)
    k_gemm_l2<<<gemm_blocks, 256>>>(ha, W2, hs);
    k_gather<false><<<gath_blocks, 256>>>(hs, b2, ha);

    // pool per graph + MLP head
    k_pool_head<<<N_GRAPHS, 64>>>(ha, bat, lw1, lb1, lw2, lb2, out);
}

// round 14
// speedup vs baseline: 1.1584x; 1.0182x over previous
#include <cuda_runtime.h>
#include <cuda_fp16.h>
#include <mma.h>

using namespace nvcuda;

#define N_NODES  100000
#define N_EDGES  1600000
#define N_GRAPHS 1000
#define D        64

// ---------------- device scratch (no allocations allowed) ----------------
__device__ int    g_deg[N_NODES];           // in-degree (0-based; self-loop added at use)
__device__ int    g_off[N_NODES];           // CSR row offsets (absolute)
__device__ int    g_cursor[N_NODES];        // fill cursors (seeded to g_off by k_scan)
__device__ int    g_total;                  // running total for atomic block offsets
__device__ int    g_csr[N_EDGES];           // src indices grouped by dst
__device__ float  g_dinv[N_NODES];          // rsqrt(deg+1)
__device__ __half g_hs[(size_t)N_NODES * D];  // fp16 prescaled GEMM outputs
__device__ __half g_ha[(size_t)N_NODES * D];  // fp16 aggregation outputs

// ---------------- degree count (deg starts at 0 via memset) ----------------
__global__ void k_deg_count(const int* __restrict__ ei) {
    int t = blockIdx.x * blockDim.x + threadIdx.x;
    if (t < N_EDGES / 4) {
        int4 d = ((const int4*)(ei + N_EDGES))[t];
        atomicAdd(&g_deg[d.x], 1);
        atomicAdd(&g_deg[d.y], 1);
        atomicAdd(&g_deg[d.z], 1);
        atomicAdd(&g_deg[d.w], 1);
    }
}

// ---------------- fused scan: absolute CSR offsets + cursor seed + dinv ----------------
__global__ __launch_bounds__(256) void k_scan() {
    __shared__ int s[256];
    __shared__ int blockOff;
    int tid = threadIdx.x;
    int i = blockIdx.x * 256 + tid;
    int deg = (i < N_NODES) ? g_deg[i] : 0;
    s[tid] = deg;
    __syncthreads();
#pragma unroll
    for (int o = 1; o < 256; o <<= 1) {
        int t = (tid >= o) ? s[tid - o] : 0;
        __syncthreads();
        s[tid] += t;
        __syncthreads();
    }
    if (tid == 255) blockOff = atomicAdd(&g_total, s[255]);
    __syncthreads();
    if (i < N_NODES) {
        int a = blockOff + s[tid] - deg;   // absolute exclusive offset
        g_off[i] = a;
        g_cursor[i] = a;
        g_dinv[i] = rsqrtf((float)(deg + 1));
    }
}

// ---------------- CSR fill: 4 edges/thread, cursor returns absolute position ----------------
__global__ __launch_bounds__(256) void k_fill(const int* __restrict__ ei) {
    int t = blockIdx.x * blockDim.x + threadIdx.x;
    if (t < N_EDGES / 4) {
        int4 s4 = ((const int4*)ei)[t];
        int4 d4 = ((const int4*)(ei + N_EDGES))[t];
        g_csr[atomicAdd(&g_cursor[d4.x], 1)] = s4.x;
        g_csr[atomicAdd(&g_cursor[d4.y], 1)] = s4.y;
        g_csr[atomicAdd(&g_cursor[d4.z], 1)] = s4.z;
        g_csr[atomicAdd(&g_cursor[d4.w], 1)] = s4.w;
    }
}

// ---------------- GEMM layer 1: hs = fp16( (x*dinv[row]) @ W1 ), x fp32 ----------------
__global__ __launch_bounds__(256) void k_gemm_l1(const float* __restrict__ in,
                                                 const float* __restrict__ W,
                                                 __half* __restrict__ hs) {
    __shared__ __align__(16) char smem_raw[128 * 68 * 4];
    __half (*Xh)[72] = (__half(*)[72])smem_raw;
    __half (*Wh)[72] = (__half(*)[72])(smem_raw + 18432);
    float  (*Out)[68] = (float(*)[68])smem_raw;

    const int tid = threadIdx.x;
    const int rowBase = blockIdx.x * 128;

#pragma unroll
    for (int i = 0; i < 4; i++) {
        int f4 = tid + i * 256;
        int r  = f4 >> 4;
        int c4 = f4 & 15;
        float4 v = ((const float4*)W)[f4];
        __half2* p = (__half2*)&Wh[r][c4 * 4];
        p[0] = __floats2half2_rn(v.x, v.y);
        p[1] = __floats2half2_rn(v.z, v.w);
    }

#pragma unroll
    for (int i = 0; i < 8; i++) {
        int f4  = tid + i * 256;
        int r   = f4 >> 4;
        int c4  = f4 & 15;
        int row = rowBase + r;
        float4 v = make_float4(0.f, 0.f, 0.f, 0.f);
        float di = 0.f;
        if (row < N_NODES) {
            v = ((const float4*)in)[(size_t)row * 16 + c4];
            di = g_dinv[row];
        }
        __half2* p = (__half2*)&Xh[r][c4 * 4];
        p[0] = __floats2half2_rn(v.x * di, v.y * di);
        p[1] = __floats2half2_rn(v.z * di, v.w * di);
    }
    __syncthreads();

    const int w = tid >> 5;
    wmma::fragment<wmma::accumulator, 16, 16, 16, float> c[4];
#pragma unroll
    for (int cg = 0; cg < 4; cg++) wmma::fill_fragment(c[cg], 0.f);
#pragma unroll
    for (int k = 0; k < 4; k++) {
        wmma::fragment<wmma::matrix_a, 16, 16, 16, __half, wmma::row_major> a;
        wmma::load_matrix_sync(a, &Xh[w * 16][k * 16], 72);
#pragma unroll
        for (int cg = 0; cg < 4; cg++) {
            wmma::fragment<wmma::matrix_b, 16, 16, 16, __half, wmma::row_major> b;
            wmma::load_matrix_sync(b, &Wh[k * 16][cg * 16], 72);
            wmma::mma_sync(c[cg], a, b, c[cg]);
        }
    }
    __syncthreads();
#pragma unroll
    for (int cg = 0; cg < 4; cg++)
        wmma::store_matrix_sync(&Out[w * 16][cg * 16], c[cg], 68, wmma::mem_row_major);
    __syncthreads();

#pragma unroll
    for (int i = 0; i < 4; i++) {
        int idx = tid + i * 256;
        int r   = idx >> 3;
        int q   = idx & 7;
        int row = rowBase + r;
        if (row < N_NODES) {
            const float* src = &Out[r][q * 8];
            __half2 ph[4];
            ph[0] = __floats2half2_rn(src[0], src[1]);
            ph[1] = __floats2half2_rn(src[2], src[3]);
            ph[2] = __floats2half2_rn(src[4], src[5]);
            ph[3] = __floats2half2_rn(src[6], src[7]);
            ((uint4*)hs)[(size_t)row * 8 + q] = *(uint4*)ph;
        }
    }
}

// ---------------- GEMM layer 2: hs = fp16( (ha*dinv[row]) @ W2 ), ha fp16 ----------------
__global__ __launch_bounds__(256) void k_gemm_l2(const __half* __restrict__ in,
                                                 const float* __restrict__ W,
                                                 __half* __restrict__ hs) {
    __shared__ __align__(16) char smem_raw[128 * 68 * 4];
    __half (*Xh)[72] = (__half(*)[72])smem_raw;
    __half (*Wh)[72] = (__half(*)[72])(smem_raw + 18432);
    float  (*Out)[68] = (float(*)[68])smem_raw;

    const int tid = threadIdx.x;
    const int rowBase = blockIdx.x * 128;

#pragma unroll
    for (int i = 0; i < 4; i++) {
        int f4 = tid + i * 256;
        int r  = f4 >> 4;
        int c4 = f4 & 15;
        float4 v = ((const float4*)W)[f4];
        __half2* p = (__half2*)&Wh[r][c4 * 4];
        p[0] = __floats2half2_rn(v.x, v.y);
        p[1] = __floats2half2_rn(v.z, v.w);
    }

#pragma unroll
    for (int i = 0; i < 4; i++) {
        int idx = tid + i * 256;        // 0..1023
        int r   = idx >> 3;             // 0..127
        int q   = idx & 7;              // 8-half chunk
        int row = rowBase + r;
        uint4 v = make_uint4(0u, 0u, 0u, 0u);
        float di = 0.f;
        if (row < N_NODES) {
            v = ((const uint4*)in)[(size_t)row * 8 + q];
            di = g_dinv[row];
        }
        __half2 ph[4];
        float2 f0 = __half22float2(*(__half2*)&v.x);
        float2 f1 = __half22float2(*(__half2*)&v.y);
        float2 f2 = __half22float2(*(__half2*)&v.z);
        float2 f3 = __half22float2(*(__half2*)&v.w);
        ph[0] = __floats2half2_rn(f0.x * di, f0.y * di);
        ph[1] = __floats2half2_rn(f1.x * di, f1.y * di);
        ph[2] = __floats2half2_rn(f2.x * di, f2.y * di);
        ph[3] = __floats2half2_rn(f3.x * di, f3.y * di);
        *(uint4*)&Xh[r][q * 8] = *(uint4*)ph;
    }
    __syncthreads();

    const int w = tid >> 5;
    wmma::fragment<wmma::accumulator, 16, 16, 16, float> c[4];
#pragma unroll
    for (int cg = 0; cg < 4; cg++) wmma::fill_fragment(c[cg], 0.f);
#pragma unroll
    for (int k = 0; k < 4; k++) {
        wmma::fragment<wmma::matrix_a, 16, 16, 16, __half, wmma::row_major> a;
        wmma::load_matrix_sync(a, &Xh[w * 16][k * 16], 72);
#pragma unroll
        for (int cg = 0; cg < 4; cg++) {
            wmma::fragment<wmma::matrix_b, 16, 16, 16, __half, wmma::row_major> b;
            wmma::load_matrix_sync(b, &Wh[k * 16][cg * 16], 72);
            wmma::mma_sync(c[cg], a, b, c[cg]);
        }
    }
    __syncthreads();
#pragma unroll
    for (int cg = 0; cg < 4; cg++)
        wmma::store_matrix_sync(&Out[w * 16][cg * 16], c[cg], 68, wmma::mem_row_major);
    __syncthreads();

#pragma unroll
    for (int i = 0; i < 4; i++) {
        int idx = tid + i * 256;
        int r   = idx >> 3;
        int q   = idx & 7;
        int row = rowBase + r;
        if (row < N_NODES) {
            const float* src = &Out[r][q * 8];
            __half2 ph[4];
            ph[0] = __floats2half2_rn(src[0], src[1]);
            ph[1] = __floats2half2_rn(src[2], src[3]);
            ph[2] = __floats2half2_rn(src[4], src[5]);
            ph[3] = __floats2half2_rn(src[6], src[7]);
            ((uint4*)hs)[(size_t)row * 8 + q] = *(uint4*)ph;
        }
    }
}

// ---------------- fp16 accumulate helpers ----------------
__device__ __forceinline__ void acc_u4(float* a, uint4 v) {
    float2 f0 = __half22float2(*(__half2*)&v.x);
    float2 f1 = __half22float2(*(__half2*)&v.y);
    float2 f2 = __half22float2(*(__half2*)&v.z);
    float2 f3 = __half22float2(*(__half2*)&v.w);
    a[0] += f0.x; a[1] += f0.y; a[2] += f1.x; a[3] += f1.y;
    a[4] += f2.x; a[5] += f2.y; a[6] += f3.x; a[7] += f3.y;
}

// 4 packed HADD2: a + v (element-wise fp16)
__device__ __forceinline__ uint4 hadd2_u4(uint4 a, uint4 v) {
    __half2* pa = (__half2*)&a;
    __half2* pv = (__half2*)&v;
    pa[0] = __hadd2(pa[0], pv[0]);
    pa[1] = __hadd2(pa[1], pv[1]);
    pa[2] = __hadd2(pa[2], pv[2]);
    pa[3] = __hadd2(pa[3], pv[3]);
    return a;
}

// ---------------- CSR gather: ha[n] = act( dinv[n]*(hs[n]+sum hs[s]) + bias ) fp16 ----------------
// 8 lanes/node. Inner loop sums groups of 8 edges with a 3-level fp16 HADD2 tree
// (28 HADD2 + one fp32 convert-add per group = 5.5 ALU ops/edge-lane vs 16 for
// naive fp32). Remainder: one 4-group tree, then exact fp32 scalars. Self term fp32.
template<bool RELU_OUT>
__global__ __launch_bounds__(256) void k_gather(const __half* __restrict__ hs,
                                                const float* __restrict__ bias,
                                                __half* __restrict__ ha) {
    int t = blockIdx.x * blockDim.x + threadIdx.x;
    int node = t >> 3;
    int lane = t & 7;
    if (node >= N_NODES) return;

    const uint4* hs4 = (const uint4*)hs;
    int start = g_off[node];
    int cnt   = g_deg[node];

    float a[8] = {0.f, 0.f, 0.f, 0.f, 0.f, 0.f, 0.f, 0.f};

    acc_u4(a, hs4[(size_t)node * 8 + lane]);   // self term (fp32 exact)

    int i = 0;
    for (; i + 8 <= cnt; i += 8) {
        int s0 = g_csr[start + i + 0];
        int s1 = g_csr[start + i + 1];
        int s2 = g_csr[start + i + 2];
        int s3 = g_csr[start + i + 3];
        int s4 = g_csr[start + i + 4];
        int s5 = g_csr[start + i + 5];
        int s6 = g_csr[start + i + 6];
        int s7 = g_csr[start + i + 7];
        uint4 v0 = hs4[(size_t)s0 * 8 + lane];
        uint4 v1 = hs4[(size_t)s1 * 8 + lane];
        uint4 v2 = hs4[(size_t)s2 * 8 + lane];
        uint4 v3 = hs4[(size_t)s3 * 8 + lane];
        uint4 v4 = hs4[(size_t)s4 * 8 + lane];
        uint4 v5 = hs4[(size_t)s5 * 8 + lane];
        uint4 v6 = hs4[(size_t)s6 * 8 + lane];
        uint4 v7 = hs4[(size_t)s7 * 8 + lane];
        // 3-level fp16 tree, one fp32 convert-add per 8 edges
        uint4 p01 = hadd2_u4(v0, v1);
        uint4 p23 = hadd2_u4(v2, v3);
        uint4 p45 = hadd2_u4(v4, v5);
        uint4 p67 = hadd2_u4(v6, v7);
        uint4 q0  = hadd2_u4(p01, p23);
        uint4 q1  = hadd2_u4(p45, p67);
        uint4 s   = hadd2_u4(q0, q1);
        acc_u4(a, s);
    }
    if (i + 4 <= cnt) {
        int s0 = g_csr[start + i + 0];
        int s1 = g_csr[start + i + 1];
        int s2 = g_csr[start + i + 2];
        int s3 = g_csr[start + i + 3];
        uint4 v0 = hs4[(size_t)s0 * 8 + lane];
        uint4 v1 = hs4[(size_t)s1 * 8 + lane];
        uint4 v2 = hs4[(size_t)s2 * 8 + lane];
        uint4 v3 = hs4[(size_t)s3 * 8 + lane];
        uint4 p01 = hadd2_u4(v0, v1);
        uint4 p23 = hadd2_u4(v2, v3);
        uint4 q   = hadd2_u4(p01, p23);
        acc_u4(a, q);
        i += 4;
    }
    for (; i < cnt; i++) {
        int s0 = g_csr[start + i];
        acc_u4(a, hs4[(size_t)s0 * 8 + lane]);
    }

    float dv = g_dinv[node];
    float4 bv0 = ((const float4*)bias)[lane * 2 + 0];
    float4 bv1 = ((const float4*)bias)[lane * 2 + 1];
    float o[8];
    o[0] = dv * a[0] + bv0.x;
    o[1] = dv * a[1] + bv0.y;
    o[2] = dv * a[2] + bv0.z;
    o[3] = dv * a[3] + bv0.w;
    o[4] = dv * a[4] + bv1.x;
    o[5] = dv * a[5] + bv1.y;
    o[6] = dv * a[6] + bv1.z;
    o[7] = dv * a[7] + bv1.w;
    if (RELU_OUT) {
#pragma unroll
        for (int j = 0; j < 8; j++) o[j] = fmaxf(o[j], 0.f);
    }
    __half2 ph[4];
    ph[0] = __floats2half2_rn(o[0], o[1]);
    ph[1] = __floats2half2_rn(o[2], o[3]);
    ph[2] = __floats2half2_rn(o[4], o[5]);
    ph[3] = __floats2half2_rn(o[6], o[7]);
    ((uint4*)ha)[(size_t)node * 8 + lane] = *(uint4*)ph;
}

// ---------------- fused mean-pool (batch is sorted) + MLP head ----------------
__global__ __launch_bounds__(64) void k_pool_head(const __half* __restrict__ ha,
                                                  const int* __restrict__ batch,
                                                  const float* __restrict__ lw1,
                                                  const float* __restrict__ lb1,
                                                  const float* __restrict__ lw2,
                                                  const float* __restrict__ lb2,
                                                  float* __restrict__ out) {
    int g = blockIdx.x;
    int tid = threadIdx.x;  // 64

    int l = 0, r = N_NODES;
    while (l < r) { int m = (l + r) >> 1; if (batch[m] < g) l = m + 1; else r = m; }
    int lo = l;
    r = N_NODES;
    while (l < r) { int m = (l + r) >> 1; if (batch[m] < g + 1) l = m + 1; else r = m; }
    int hi = l;

    float acc = 0.f;
    for (int n = lo; n < hi; n++) acc += __half2float(ha[(size_t)n * 64 + tid]);
    int cnt = hi - lo;
    float pooled = acc / (float)(cnt > 0 ? cnt : 1);

    __shared__ float sp[64];
    __shared__ float sz[32];
    sp[tid] = pooled;
    __syncthreads();

    if (tid < 32) {
        float z = lb1[tid];
#pragma unroll 8
        for (int k = 0; k < 64; k++) z += sp[k] * lw1[k * 32 + tid];
        sz[tid] = fmaxf(z, 0.f);
    }
    __syncthreads();

    if (tid < 8) {
        float o = lb2[tid];
#pragma unroll
        for (int j = 0; j < 32; j++) o += sz[j] * lw2[j * 8 + tid];
        out[g * 8 + tid] = o;
    }
}

// ---------------- launch ----------------
extern "C" void kernel_launch(void* const* d_in, const int* in_sizes, int n_in,
                              void* d_out, int out_size) {
    const float* x   = (const float*)d_in[0];
    const int*   ei  = (const int*)d_in[1];
    const int*   bat = (const int*)d_in[2];
    const float* W1  = (const float*)d_in[3];
    const float* b1  = (const float*)d_in[4];
    const float* W2  = (const float*)d_in[5];
    const float* b2  = (const float*)d_in[6];
    const float* lw1 = (const float*)d_in[7];
    const float* lb1 = (const float*)d_in[8];
    const float* lw2 = (const float*)d_in[9];
    const float* lb2 = (const float*)d_in[10];
    float* out = (float*)d_out;

    __half *hs, *ha;
    int *degp, *totp;
    cudaGetSymbolAddress((void**)&hs,   g_hs);
    cudaGetSymbolAddress((void**)&ha,   g_ha);
    cudaGetSymbolAddress((void**)&degp, g_deg);
    cudaGetSymbolAddress((void**)&totp, g_total);

    static cudaStream_t s2 = nullptr;
    static cudaEvent_t evFork = nullptr, evJoin = nullptr;
    if (s2 == nullptr) {
        cudaStreamCreateWithFlags(&s2, cudaStreamNonBlocking);
        cudaEventCreateWithFlags(&evFork, cudaEventDisableTiming);
        cudaEventCreateWithFlags(&evJoin, cudaEventDisableTiming);
    }

    const int nblk = (N_NODES + 255) / 256;
    const int gemm_blocks = (N_NODES + 127) / 128;
    const int gath_blocks = (N_NODES * 8 + 255) / 256;
    const int e4blk = (N_EDGES / 4 + 255) / 256;

    // serial prefix on main: zero deg/total, count degrees, fused scan(+cursor+dinv)
    cudaMemsetAsync(degp, 0, N_NODES * sizeof(int), 0);
    cudaMemsetAsync(totp, 0, sizeof(int), 0);
    k_deg_count<<<e4blk, 256>>>(ei);
    k_scan<<<nblk, 256>>>();

    // fork: fill on s2 || GEMM1 on main (balanced ~10-15us each)
    cudaEventRecord(evFork, 0);
    cudaStreamWaitEvent(s2, evFork, 0);

    k_fill<<<e4blk, 256, 0, s2>>>(ei);

    k_gemm_l1<<<gemm_blocks, 256>>>(x, W1, hs);   // concurrent

    cudaEventRecord(evJoin, s2);
    cudaStreamWaitEvent(0, evJoin, 0);

    // layer 1 aggregation: ha = relu(dinv*(sum)+b1) in fp16
    k_gather<true><<<gath_blocks, 256>>>(hs, b1, ha);

    // layer 2: fp16-input GEMM (dinv applied in staging), gather (no relu)
    k_gemm_l2<<<gemm_blocks, 256>>>(ha, W2, hs);
    k_gather<false><<<gath_blocks, 256>>>(hs, b2, ha);

    // pool per graph + MLP head
    k_pool_head<<<N_GRAPHS, 64>>>(ha, bat, lw1, lb1, lw2, lb2, out);
}